// round 1
// baseline (speedup 1.0000x reference)
#include <cuda_runtime.h>
#include <stdint.h>

// carry_save_adder: exact-binary reduction.
// S_b = sum over kept i of value(x[b,i,:]) ; out bits = S_b & 0xFFFF, carry = S_b >> 16.
// One warp per batch row: 256 float4 loads split 8 per lane (fully coalesced),
// integer popcount-style accumulate, warp shfl reduction, 17 float writes.

__global__ void __launch_bounds__(256)
csa_kernel(const float4* __restrict__ x, const int* __restrict__ mask,
           float* __restrict__ out, int B)
{
    const unsigned FULL = 0xFFFFFFFFu;
    int lane = threadIdx.x & 31;
    int warp = (blockIdx.x * blockDim.x + threadIdx.x) >> 5;

    // Build the 64-bit keep-mask once per warp (indices 0,1 always kept).
    int m_lo = mask[lane];
    int m_hi = mask[lane + 32];
    unsigned mb_lo = __ballot_sync(FULL, m_lo > 0) | 3u;
    unsigned mb_hi = __ballot_sync(FULL, m_hi > 0);

    if (warp >= B) return;

    const float4* row = x + (size_t)warp * 256;  // 1024 floats / 4

    unsigned sum = 0;
    #pragma unroll
    for (int t = 0; t < 8; ++t) {
        int c  = lane + 32 * t;        // float4 chunk 0..255 within the row
        int i  = c >> 2;               // value index 0..63
        int j0 = (c & 3) << 2;         // starting bit position (0,4,8,12)
        unsigned keep = (i < 32) ? ((mb_lo >> i) & 1u) : ((mb_hi >> (i - 32)) & 1u);

        float4 v = __ldg(&row[c]);
        unsigned contrib =
              ((__float_as_uint(v.x) != 0u) ? (1u << (j0 + 0)) : 0u)
            | ((__float_as_uint(v.y) != 0u) ? (1u << (j0 + 1)) : 0u)
            | ((__float_as_uint(v.z) != 0u) ? (1u << (j0 + 2)) : 0u)
            | ((__float_as_uint(v.w) != 0u) ? (1u << (j0 + 3)) : 0u);
        sum += keep ? contrib : 0u;
    }

    // Warp reduction: S_b fits in 22 bits.
    #pragma unroll
    for (int off = 16; off; off >>= 1)
        sum += __shfl_xor_sync(FULL, sum, off);

    // Write output bits (lanes 0..15) and carry (lane 16).
    if (lane < 16)
        out[(size_t)warp * 16 + lane] = (float)((sum >> lane) & 1u);
    else if (lane == 16)
        out[(size_t)B * 16 + warp] = (float)(sum >> 16);
}

extern "C" void kernel_launch(void* const* d_in, const int* in_sizes, int n_in,
                              void* d_out, int out_size)
{
    const float4* x   = (const float4*)d_in[0];   // (B, 64, 16) float32
    const int*    msk = (const int*)d_in[1];      // (64,) int32
    float*        out = (float*)d_out;            // B*16 output bits, then B carries

    int B = in_sizes[0] / 1024;                   // 64*16 floats per batch row

    int threads = 256;                            // 8 warps/block
    int warps_needed = B;
    int blocks = (warps_needed * 32 + threads - 1) / threads;
    csa_kernel<<<blocks, threads>>>(x, msk, out, B);
}